// round 13
// baseline (speedup 1.0000x reference)
#include <cuda_runtime.h>

#define BB   64
#define MM   100
#define NN   4000
#define KK   4100          // N + M (proposal_append_gt)
#define NB   1024          // priority buckets per group
#define NCLS 80
#define BATCH_PER_IMG 512
#define NUM_FG_TARGET 128
#define ST   1024          // sample_kernel threads
#define SIT  5             // ceil(KK / ST)
#define LPI  1280          // lanes per image in iou_kernel (5 CTAs * 256)
#define PPT  4             // proposals per thread
#define TBF  0.85f         // bg candidate priority threshold (ballot-verified)

// Scratch (static __device__ — no allocation)
__device__ float         g_mv[BB * KK];
__device__ unsigned char g_mi[BB * KK];

// ---------------------------------------------------------------------------
// Per-pair update (R9-proven exact formulation, rel_err 0.0):
//   max(x,0) = 0.5*(x+|x|)  (exact; |x| is a free operand modifier)
//   inter4 = (w+|w|)*(h+|h|) = 4*inter  (exact power-of-2 scaling)
//   argmax: iou = inter/(S-inter) monotone in inter/S -> cross-multiply.
// alu pipe: 4 FMNMX + FSETP + 3 SEL;  fma pipe: 4 FADD + 3 FMUL + FADD(S)
// ---------------------------------------------------------------------------
__device__ __forceinline__ void iou_upd(float gx, float gy, float gz, float gw,
                                        float S, const float4& a,
                                        float& bi4, float& bS, int& bm, int m) {
    float lx = fmaxf(gx, a.x), ly = fmaxf(gy, a.y);
    float rx = fminf(gz, a.z), ry = fminf(gw, a.w);
    float w = rx - lx, h = ry - ly;
    float aw = w + fabsf(w);
    float ah = h + fabsf(h);
    float inter4 = aw * ah;
    if (inter4 * bS > bi4 * S) { bi4 = inter4; bS = S; bm = m; }
}

__device__ __forceinline__ void iou_finish(float bi4, float bS, int bm,
                                           int b, int k) {
    float uni = fmaf(-0.25f, bi4, bS);      // = rnd(S - inter), bit-identical
    size_t o = (size_t)b * KK + k;
    g_mv[o] = __fdiv_rn(0.25f * bi4, uni);  // all-zero case: 0/1 = 0 (bS init 1)
    g_mi[o] = (unsigned char)bm;
}

// ---------------------------------------------------------------------------
// Kernel 1: per-(image, proposal) max-IoU matching.
// 4 proposals per thread (8 independent select-chains: [prop][parity]) —
// amortizes gt LDS + loop control over 4 pairs and covers the ~21-cycle
// FSETP->SEL chain latency with ILP instead of occupancy.
// Slots j=0..2 are always proposals (k <= 3839 < NN); only j=3 branches.
// ---------------------------------------------------------------------------
__global__ __launch_bounds__(256) void iou_kernel(const float* __restrict__ gt,
                                                  const float* __restrict__ prop) {
    const int b   = blockIdx.y;
    const int tid = threadIdx.x;
    __shared__ float4 sgt[MM];
    __shared__ float  sarea[MM];

    if (tid < MM) {
        float4 g = reinterpret_cast<const float4*>(gt)[b * MM + tid];
        sgt[tid]   = g;
        sarea[tid] = (g.z - g.x) * (g.w - g.y);
    }
    __syncthreads();

    const float4* pr = reinterpret_cast<const float4*>(prop) + (size_t)b * NN;

    const int kbase = blockIdx.x * 256 + tid;   // [0, 1280)
    float4 a[PPT];
    float  areaA[PPT];
    bool   act[PPT];
    #pragma unroll
    for (int j = 0; j < PPT; j++) {
        int k = kbase + j * LPI;
        act[j] = (k < KK);
        float4 box;
        if (j < 3) {
            box = pr[k];                        // k <= 3839 < NN always
        } else {
            box = sgt[0];                       // dummy for inactive lanes
            if (act[j]) box = (k < NN) ? pr[k] : sgt[k - NN];
        }
        a[j] = box;
        areaA[j] = (box.z - box.x) * (box.w - box.y);
    }

    // chains [proposal][parity]; bS holds S of current best; fully unrolled
    // register arrays.
    float bi[PPT][2], bS[PPT][2];
    int   bm[PPT][2];
    #pragma unroll
    for (int j = 0; j < PPT; j++) {
        bi[j][0] = 0.f; bS[j][0] = 1.f; bm[j][0] = 0;
        bi[j][1] = 0.f; bS[j][1] = 1.f; bm[j][1] = 1;
    }

    #pragma unroll 2
    for (int m = 0; m < MM; m += 2) {
        {
            float4 g = sgt[m];
            float ga = sarea[m];
            #pragma unroll
            for (int j = 0; j < PPT; j++)
                iou_upd(g.x, g.y, g.z, g.w, ga + areaA[j], a[j],
                        bi[j][0], bS[j][0], bm[j][0], m);
        }
        {
            float4 g = sgt[m + 1];
            float ga = sarea[m + 1];
            #pragma unroll
            for (int j = 0; j < PPT; j++)
                iou_upd(g.x, g.y, g.z, g.w, ga + areaA[j], a[j],
                        bi[j][1], bS[j][1], bm[j][1], m + 1);
        }
    }

    // merge parities (first-max tie-break: equal value -> lower index)
    #pragma unroll
    for (int j = 0; j < PPT; j++) {
        if (act[j]) {
            float c0 = bi[j][0] * bS[j][1], c1 = bi[j][1] * bS[j][0];
            bool useE = (c0 > c1) || (c0 == c1 && bm[j][0] < bm[j][1]);
            iou_finish(useE ? bi[j][0] : bi[j][1],
                       useE ? bS[j][0] : bS[j][1],
                       useE ? bm[j][0] : bm[j][1],
                       b, kbase + j * LPI);
        }
    }
}

// ---------------------------------------------------------------------------
// Kernel 2: per-image fg/bg subsampling, SPLIT 2 CTAs per image:
// blockIdx.y == 0 -> fg CTA (selects top-128 fg, writes rows [0, num_fg))
// blockIdx.y == 1 -> bg CTA (selects top-(512-num_fg) bg, writes rows
//                    [num_fg, 512) including the invalid tail).
// Each CTA histograms/scans/ranks only ITS group (NB buckets).
// bg CTA uses the TBF priority threshold (ballot-verified; exact fallback).
// ---------------------------------------------------------------------------
__global__ __launch_bounds__(ST) void sample_kernel(const float* __restrict__ pri,
                                                    const void*  __restrict__ gtcls,
                                                    float* __restrict__ out) {
    const int  b    = blockIdx.x;
    const bool isbg = (blockIdx.y != 0);
    const int  tid  = threadIdx.x;

    __shared__ float          s_pri[KK];
    __shared__ unsigned short s_list[KK];
    __shared__ int            s_cnt[NB];      // histogram, then scatter cursor
    __shared__ int            s_P[NB + 1];    // ascending exclusive prefix
    __shared__ unsigned short s_ord[BATCH_PER_IMG];
    __shared__ int            s_wsum[33];
    __shared__ int            s_nz;
    __shared__ int            s_nown;         // #elements of own group
    __shared__ int            s_cbg;          // #own elements with p >= TBF

    if (tid == 0) { s_nz = 0; s_nown = 0; s_cbg = 0; }
    s_cnt[tid] = 0;                           // NB == ST: one store per thread
    __syncthreads();

    // fg CTA only: gt_classes dtype detect (int64 -> high words all zero).
    if (!isbg && tid < 64) {
        const int* w = (const int*)gtcls;
        if (w[2 * tid + 1] != 0) atomicOr(&s_nz, 1);
    }

    const float* prib = pri  + (size_t)b * KK;
    const float* mvb  = g_mv + (size_t)b * KK;

    // P0: load priority + own-group flag; ballot-count group size and
    // above-threshold candidates (one shared atomic per warp).
    float pv[SIT];
    bool  ov[SIT];
    unsigned nown = 0, cbg = 0;
    #pragma unroll
    for (int it = 0; it < SIT; it++) {
        int k = tid + it * ST;
        float p = -1.f;
        bool own = false;
        if (k < KK) {
            p = prib[k];
            s_pri[k] = p;
            bool fg = (mvb[k] >= 0.5f);
            own = isbg ? !fg : fg;
        }
        pv[it] = p;
        ov[it] = own;
        unsigned m1 = __ballot_sync(0xffffffffu, own);
        unsigned m2 = __ballot_sync(0xffffffffu, own && p >= TBF);
        if ((tid & 31) == 0) { nown += __popc(m1); cbg += __popc(m2); }
    }
    if ((tid & 31) == 0) {
        if (nown) atomicAdd(&s_nown, (int)nown);
        if (cbg)  atomicAdd(&s_cbg, (int)cbg);
    }
    __syncthreads();

    // bg: threshold valid iff >= 512 bg have p >= TBF (then top-512 bg all
    // have p >= TBF; excluded are strictly lower). fg: all elements included.
    const float tbeff = (isbg && s_cbg >= BATCH_PER_IMG) ? TBF : -1e30f;

    // P1: histogram own candidates.
    short myb[SIT];
    #pragma unroll
    for (int it = 0; it < SIT; it++) {
        short bs = -1;
        if (ov[it] && pv[it] >= tbeff) {
            int bk = (int)(pv[it] * (float)NB);
            bk = bk < 0 ? 0 : (bk > NB - 1 ? NB - 1 : bk);
            bs = (short)bk;
            atomicAdd(&s_cnt[bk], 1);
        }
        myb[it] = bs;
    }
    __syncthreads();

    // Exclusive scan over NB=1024 counts (1 per thread).
    int v = s_cnt[tid];
    int lane = tid & 31, wid = tid >> 5;
    int incl = v;
    #pragma unroll
    for (int d = 1; d < 32; d <<= 1) {
        int n = __shfl_up_sync(0xffffffffu, incl, d);
        if (lane >= d) incl += n;
    }
    if (lane == 31) s_wsum[wid] = incl;
    __syncthreads();
    if (tid == 0) {
        int s = 0;
        #pragma unroll
        for (int i = 0; i < 32; i++) { int c = s_wsum[i]; s_wsum[i] = s; s += c; }
        s_wsum[32] = s;
    }
    __syncthreads();
    int ex = s_wsum[wid] + incl - v;
    s_P[tid]  = ex;
    s_cnt[tid] = ex;                    // scatter cursor
    if (tid == 0) s_P[NB] = s_wsum[32];
    __syncthreads();

    const int candTot = s_P[NB];
    const int limit   = isbg ? BATCH_PER_IMG : NUM_FG_TARGET;

    // P2: scatter candidate indices into buckets.
    #pragma unroll
    for (int it = 0; it < SIT; it++) {
        if (myb[it] >= 0) {
            int k = tid + it * ST;
            int pos = atomicAdd(&s_cnt[myb[it]], 1);
            s_list[pos] = (unsigned short)k;
        }
    }
    __syncthreads();

    // P3: exact descending rank (higher bucket = higher priority); tie-break
    // = reversed stable argsort: equal priority -> higher index first.
    #pragma unroll
    for (int it = 0; it < SIT; it++) {
        if (myb[it] >= 0) {
            int bk = myb[it];
            int lo = s_P[bk], hi = s_P[bk + 1];
            int base = candTot - hi;        // candidates in strictly-higher buckets
            if (base < limit) {
                int k = tid + it * ST;
                float p = pv[it];
                int r = base;
                for (int j = lo; j < hi; j++) {
                    int o = s_list[j];
                    float po = s_pri[o];
                    if (po > p || (po == p && o > k)) r++;
                }
                if (r < limit) s_ord[r] = (unsigned short)k;
            }
        }
    }
    __syncthreads();

    // Output. Both CTAs derive num_fg from their own group count.
    const int nfg    = isbg ? (KK - s_nown) : s_nown;
    const int num_fg = nfg < NUM_FG_TARGET ? nfg : NUM_FG_TARGET;
    const int S    = BB * BATCH_PER_IMG;
    const int base = b * BATCH_PER_IMG + tid;

    if (!isbg) {
        // fg rows [0, num_fg): always valid, mv >= 0.5 so class from gt.
        if (tid < num_fg) {
            int k  = (int)s_ord[tid];
            float mv = mvb[k];
            int   mi = (int)g_mi[(size_t)b * KK + k];
            int cls = (s_nz == 0) ? (int)((const long long*)gtcls)[b * MM + mi]
                                  : ((const int*)gtcls)[b * MM + mi];
            out[base]         = mv;
            out[S + base]     = (float)k;
            out[2 * S + base] = (float)cls;
            out[3 * S + base] = (float)mi;
            out[4 * S + base] = 1.f;
        }
    } else {
        // bg rows [num_fg, 512) incl. invalid tail; bg class is NCLS.
        if (tid >= num_fg && tid < BATCH_PER_IMG) {
            int nbg    = KK - nfg;
            int rem    = BATCH_PER_IMG - num_fg;
            int num_bg = nbg < rem ? nbg : rem;
            int tot    = num_fg + num_bg;
            float o_iou = 0.f;
            int o_idx = -1, o_cls = -1, o_gt = -1, o_val = 0;
            if (tid < tot) {
                int k = (int)s_ord[tid - num_fg];
                o_iou = mvb[k];
                o_idx = k;
                o_cls = NCLS;
                o_gt  = (int)g_mi[(size_t)b * KK + k];
                o_val = 1;
            }
            out[base]         = o_iou;
            out[S + base]     = (float)o_idx;
            out[2 * S + base] = (float)o_cls;
            out[3 * S + base] = (float)o_gt;
            out[4 * S + base] = (float)o_val;
        }
    }
}

// ---------------------------------------------------------------------------
extern "C" void kernel_launch(void* const* d_in, const int* in_sizes, int n_in,
                              void* d_out, int out_size) {
    const float* gt   = (const float*)d_in[0];   // [B, M, 4]
    const float* prop = (const float*)d_in[1];   // [B, N, 4]
    const void*  gtc  = d_in[2];                 // [B, M] int64 or int32
    const float* pri  = (const float*)d_in[3];   // [B, K]
    float* out = (float*)d_out;

    iou_kernel<<<dim3(5, BB), 256>>>(gt, prop);
    sample_kernel<<<dim3(BB, 2), ST>>>(pri, gtc, out);
}

// round 14
// speedup vs baseline: 1.3674x; 1.3674x over previous
#include <cuda_runtime.h>

#define BB   64
#define MM   100
#define NN   4000
#define KK   4100          // N + M (proposal_append_gt)
#define NB   1024          // priority buckets per group
#define NCLS 80
#define BATCH_PER_IMG 512
#define NUM_FG_TARGET 128
#define ST   1024          // sample_kernel threads
#define SIT  5             // ceil(KK / ST)
#define LPI  2304          // lanes per image in iou_kernel (9 CTAs * 256)
#define TBF  0.85f         // bg candidate priority threshold (ballot-verified)

// Scratch (static __device__ — no allocation). {mv, (float)mi} per element.
__device__ float2 g_pk[BB * KK];

// ---------------------------------------------------------------------------
// Per-pair update (R9-proven exact formulation, rel_err 0.0):
//   max(x,0) = 0.5*(x+|x|)  (exact; |x| is a free operand modifier)
//   inter4 = (w+|w|)*(h+|h|) = 4*inter  (exact power-of-2 scaling)
//   argmax: iou = inter/(S-inter) monotone in inter/S -> cross-multiply.
// ---------------------------------------------------------------------------
__device__ __forceinline__ void iou_upd(float gx, float gy, float gz, float gw,
                                        float S, const float4& a,
                                        float& bi4, float& bS, int& bm, int m) {
    float lx = fmaxf(gx, a.x), ly = fmaxf(gy, a.y);
    float rx = fminf(gz, a.z), ry = fminf(gw, a.w);
    float w = rx - lx, h = ry - ly;
    float aw = w + fabsf(w);
    float ah = h + fabsf(h);
    float inter4 = aw * ah;
    if (inter4 * bS > bi4 * S) { bi4 = inter4; bS = S; bm = m; }
}

__device__ __forceinline__ void iou_finish(float bi4, float bS, int bm,
                                           int b, int k) {
    float uni = fmaf(-0.25f, bi4, bS);      // = rnd(S - inter), bit-identical
    float2 v;
    v.x = __fdiv_rn(0.25f * bi4, uni);      // all-zero case: 0/1 = 0 (bS init 1)
    v.y = (float)bm;                         // mi in [0,100) exact in float
    g_pk[(size_t)b * KK + k] = v;            // single STG.64
}

// ---------------------------------------------------------------------------
// Kernel 1: per-(image, proposal) max-IoU matching.  (R9 structure: 2
// proposals per thread, 2 parity chains per proposal, unroll 4.)
// ---------------------------------------------------------------------------
__global__ __launch_bounds__(256) void iou_kernel(const float* __restrict__ gt,
                                                  const float* __restrict__ prop) {
    const int b   = blockIdx.y;
    const int tid = threadIdx.x;
    __shared__ float4 sgt[MM];
    __shared__ float  sarea[MM];

    if (tid < MM) {
        float4 g = reinterpret_cast<const float4*>(gt)[b * MM + tid];
        sgt[tid]   = g;
        sarea[tid] = (g.z - g.x) * (g.w - g.y);
    }
    __syncthreads();

    const float4* pr = reinterpret_cast<const float4*>(prop) + (size_t)b * NN;

    const int k0 = blockIdx.x * 256 + tid;   // [0, 2304) -> always a proposal (< NN)
    const int k1 = k0 + LPI;                 // [2304, 4608) -> may be gt or OOB
    float4 a0 = pr[k0];
    bool has1 = (k1 < KK);
    float4 a1 = a0;
    if (has1) a1 = (k1 < NN) ? pr[k1] : sgt[k1 - NN];

    float areaA0 = (a0.z - a0.x) * (a0.w - a0.y);
    float areaA1 = (a1.z - a1.x) * (a1.w - a1.y);

    // chains: [proposal][parity]; bS holds S (=areaG+areaA) of current best
    float bi0e = 0.f, bS0e = 1.f; int bm0e = 0;
    float bi0o = 0.f, bS0o = 1.f; int bm0o = 1;
    float bi1e = 0.f, bS1e = 1.f; int bm1e = 0;
    float bi1o = 0.f, bS1o = 1.f; int bm1o = 1;

    #pragma unroll 4
    for (int m = 0; m < MM; m += 2) {
        {
            float4 g = sgt[m];
            float ga = sarea[m];
            iou_upd(g.x, g.y, g.z, g.w, ga + areaA0, a0, bi0e, bS0e, bm0e, m);
            iou_upd(g.x, g.y, g.z, g.w, ga + areaA1, a1, bi1e, bS1e, bm1e, m);
        }
        {
            float4 g = sgt[m + 1];
            float ga = sarea[m + 1];
            iou_upd(g.x, g.y, g.z, g.w, ga + areaA0, a0, bi0o, bS0o, bm0o, m + 1);
            iou_upd(g.x, g.y, g.z, g.w, ga + areaA1, a1, bi1o, bS1o, bm1o, m + 1);
        }
    }

    // merge parities (first-max tie-break: equal value -> lower index)
    {
        float c0 = bi0e * bS0o, c1 = bi0o * bS0e;
        bool useE = (c0 > c1) || (c0 == c1 && bm0e < bm0o);
        iou_finish(useE ? bi0e : bi0o, useE ? bS0e : bS0o, useE ? bm0e : bm0o, b, k0);
    }
    if (has1) {
        float c0 = bi1e * bS1o, c1 = bi1o * bS1e;
        bool useE = (c0 > c1) || (c0 == c1 && bm1e < bm1o);
        iou_finish(useE ? bi1e : bi1o, useE ? bS1e : bS1o, useE ? bm1e : bm1o, b, k1);
    }
}

// ---------------------------------------------------------------------------
// Kernel 2: per-image fg/bg subsampling, SPLIT 2 CTAs per image:
// blockIdx.y == 0 -> fg CTA (selects top-128 fg, writes rows [0, num_fg))
// blockIdx.y == 1 -> bg CTA (selects top-(512-num_fg) bg, writes rows
//                    [num_fg, 512) including the invalid tail).
// Each CTA histograms/scans/ranks only ITS group (NB buckets).
// bg CTA uses the TBF priority threshold (ballot-verified; exact fallback).
// ---------------------------------------------------------------------------
__global__ __launch_bounds__(ST) void sample_kernel(const float* __restrict__ pri,
                                                    const void*  __restrict__ gtcls,
                                                    float* __restrict__ out) {
    const int  b    = blockIdx.x;
    const bool isbg = (blockIdx.y != 0);
    const int  tid  = threadIdx.x;

    __shared__ float          s_pri[KK];
    __shared__ unsigned short s_list[KK];
    __shared__ int            s_cnt[NB];      // histogram, then scatter cursor
    __shared__ int            s_P[NB + 1];    // ascending exclusive prefix
    __shared__ unsigned short s_ord[BATCH_PER_IMG];
    __shared__ int            s_wsum[33];
    __shared__ int            s_nz;
    __shared__ int            s_nown;         // #elements of own group
    __shared__ int            s_cbg;          // #own elements with p >= TBF

    if (tid == 0) { s_nz = 0; s_nown = 0; s_cbg = 0; }
    s_cnt[tid] = 0;                           // NB == ST: one store per thread
    __syncthreads();

    // fg CTA only: gt_classes dtype detect (int64 -> high words all zero).
    if (!isbg && tid < 64) {
        const int* w = (const int*)gtcls;
        if (w[2 * tid + 1] != 0) atomicOr(&s_nz, 1);
    }

    const float*  prib = pri  + (size_t)b * KK;
    const float2* pkb  = g_pk + (size_t)b * KK;

    // P0: load priority + own-group flag; ballot-count group size and
    // above-threshold candidates (one shared atomic per warp).
    float pv[SIT];
    bool  ov[SIT];
    unsigned nown = 0, cbg = 0;
    #pragma unroll
    for (int it = 0; it < SIT; it++) {
        int k = tid + it * ST;
        float p = -1.f;
        bool own = false;
        if (k < KK) {
            p = prib[k];
            s_pri[k] = p;
            bool fg = (pkb[k].x >= 0.5f);
            own = isbg ? !fg : fg;
        }
        pv[it] = p;
        ov[it] = own;
        unsigned m1 = __ballot_sync(0xffffffffu, own);
        unsigned m2 = __ballot_sync(0xffffffffu, own && p >= TBF);
        if ((tid & 31) == 0) { nown += __popc(m1); cbg += __popc(m2); }
    }
    if ((tid & 31) == 0) {
        if (nown) atomicAdd(&s_nown, (int)nown);
        if (cbg)  atomicAdd(&s_cbg, (int)cbg);
    }
    __syncthreads();

    // bg: threshold valid iff >= 512 bg have p >= TBF (then top-512 bg all
    // have p >= TBF; excluded are strictly lower). fg: all elements included.
    const float tbeff = (isbg && s_cbg >= BATCH_PER_IMG) ? TBF : -1e30f;

    // P1: histogram own candidates.
    short myb[SIT];
    #pragma unroll
    for (int it = 0; it < SIT; it++) {
        short bs = -1;
        if (ov[it] && pv[it] >= tbeff) {
            int bk = (int)(pv[it] * (float)NB);
            bk = bk < 0 ? 0 : (bk > NB - 1 ? NB - 1 : bk);
            bs = (short)bk;
            atomicAdd(&s_cnt[bk], 1);
        }
        myb[it] = bs;
    }
    __syncthreads();

    // Exclusive scan over NB=1024 counts (1 per thread).
    int v = s_cnt[tid];
    int lane = tid & 31, wid = tid >> 5;
    int incl = v;
    #pragma unroll
    for (int d = 1; d < 32; d <<= 1) {
        int n = __shfl_up_sync(0xffffffffu, incl, d);
        if (lane >= d) incl += n;
    }
    if (lane == 31) s_wsum[wid] = incl;
    __syncthreads();
    if (tid == 0) {
        int s = 0;
        #pragma unroll
        for (int i = 0; i < 32; i++) { int c = s_wsum[i]; s_wsum[i] = s; s += c; }
        s_wsum[32] = s;
    }
    __syncthreads();
    int ex = s_wsum[wid] + incl - v;
    s_P[tid]  = ex;
    s_cnt[tid] = ex;                    // scatter cursor
    if (tid == 0) s_P[NB] = s_wsum[32];
    __syncthreads();

    const int candTot = s_P[NB];
    const int limit   = isbg ? BATCH_PER_IMG : NUM_FG_TARGET;

    // P2: scatter candidate indices into buckets.
    #pragma unroll
    for (int it = 0; it < SIT; it++) {
        if (myb[it] >= 0) {
            int k = tid + it * ST;
            int pos = atomicAdd(&s_cnt[myb[it]], 1);
            s_list[pos] = (unsigned short)k;
        }
    }
    __syncthreads();

    // P3: exact descending rank (higher bucket = higher priority); tie-break
    // = reversed stable argsort: equal priority -> higher index first.
    #pragma unroll
    for (int it = 0; it < SIT; it++) {
        if (myb[it] >= 0) {
            int bk = myb[it];
            int lo = s_P[bk], hi = s_P[bk + 1];
            int base = candTot - hi;        // candidates in strictly-higher buckets
            if (base < limit) {
                int k = tid + it * ST;
                float p = pv[it];
                int r = base;
                for (int j = lo; j < hi; j++) {
                    int o = s_list[j];
                    float po = s_pri[o];
                    if (po > p || (po == p && o > k)) r++;
                }
                if (r < limit) s_ord[r] = (unsigned short)k;
            }
        }
    }
    __syncthreads();

    // Output. Both CTAs derive num_fg from their own group count.
    const int nfg    = isbg ? (KK - s_nown) : s_nown;
    const int num_fg = nfg < NUM_FG_TARGET ? nfg : NUM_FG_TARGET;
    const int S    = BB * BATCH_PER_IMG;
    const int base = b * BATCH_PER_IMG + tid;

    if (!isbg) {
        // fg rows [0, num_fg): always valid, mv >= 0.5 so class from gt.
        if (tid < num_fg) {
            int k  = (int)s_ord[tid];
            float2 pk = pkb[k];               // one LDG.64: {mv, mi}
            int   mi = (int)pk.y;
            int cls = (s_nz == 0) ? (int)((const long long*)gtcls)[b * MM + mi]
                                  : ((const int*)gtcls)[b * MM + mi];
            out[base]         = pk.x;
            out[S + base]     = (float)k;
            out[2 * S + base] = (float)cls;
            out[3 * S + base] = pk.y;
            out[4 * S + base] = 1.f;
        }
    } else {
        // bg rows [num_fg, 512) incl. invalid tail; bg class is NCLS.
        if (tid >= num_fg && tid < BATCH_PER_IMG) {
            int nbg    = KK - nfg;
            int rem    = BATCH_PER_IMG - num_fg;
            int num_bg = nbg < rem ? nbg : rem;
            int tot    = num_fg + num_bg;
            float o_iou = 0.f;
            float o_idx = -1.f, o_cls = -1.f, o_gt = -1.f, o_val = 0.f;
            if (tid < tot) {
                int k = (int)s_ord[tid - num_fg];
                float2 pk = pkb[k];           // one LDG.64: {mv, mi}
                o_iou = pk.x;
                o_idx = (float)k;
                o_cls = (float)NCLS;
                o_gt  = pk.y;
                o_val = 1.f;
            }
            out[base]         = o_iou;
            out[S + base]     = o_idx;
            out[2 * S + base] = o_cls;
            out[3 * S + base] = o_gt;
            out[4 * S + base] = o_val;
        }
    }
}

// ---------------------------------------------------------------------------
extern "C" void kernel_launch(void* const* d_in, const int* in_sizes, int n_in,
                              void* d_out, int out_size) {
    const float* gt   = (const float*)d_in[0];   // [B, M, 4]
    const float* prop = (const float*)d_in[1];   // [B, N, 4]
    const void*  gtc  = d_in[2];                 // [B, M] int64 or int32
    const float* pri  = (const float*)d_in[3];   // [B, K]
    float* out = (float*)d_out;

    iou_kernel<<<dim3(9, BB), 256>>>(gt, prop);
    sample_kernel<<<dim3(BB, 2), ST>>>(pri, gtc, out);
}

// round 15
// speedup vs baseline: 1.3689x; 1.0011x over previous
#include <cuda_runtime.h>

#define BB   64
#define MM   100
#define NN   4000
#define KK   4100          // N + M (proposal_append_gt)
#define NB   1024          // priority buckets per group
#define NCLS 80
#define BATCH_PER_IMG 512
#define NUM_FG_TARGET 128
#define ST   1024          // sample_kernel threads
#define SIT  5             // ceil(KK / ST)
#define LPI  2304          // lanes per image in iou_kernel (9 CTAs * 256)
#define TBF  0.85f         // bg candidate priority threshold (ballot-verified)

// Scratch (static __device__ — no allocation). {mv, (float)mi} per element.
__device__ float2 g_pk[BB * KK];

// ---------------------------------------------------------------------------
// Per-pair update (R9/R14-proven exact formulation, rel_err 0.0):
//   max(x,0) = 0.5*(x+|x|)  (exact; |x| is a free operand modifier)
//   inter4 = (w+|w|)*(h+|h|) = 4*inter  (exact power-of-2 scaling)
//   argmax: iou = inter/(S-inter) monotone in inter/S -> cross-multiply.
// ---------------------------------------------------------------------------
__device__ __forceinline__ void iou_upd(float gx, float gy, float gz, float gw,
                                        float S, const float4& a,
                                        float& bi4, float& bS, int& bm, int m) {
    float lx = fmaxf(gx, a.x), ly = fmaxf(gy, a.y);
    float rx = fminf(gz, a.z), ry = fminf(gw, a.w);
    float w = rx - lx, h = ry - ly;
    float aw = w + fabsf(w);
    float ah = h + fabsf(h);
    float inter4 = aw * ah;
    if (inter4 * bS > bi4 * S) { bi4 = inter4; bS = S; bm = m; }
}

__device__ __forceinline__ void iou_finish(float bi4, float bS, int bm,
                                           int b, int k) {
    float uni = fmaf(-0.25f, bi4, bS);      // = rnd(S - inter), bit-identical
    float2 v;
    v.x = __fdiv_rn(0.25f * bi4, uni);      // all-zero case: 0/1 = 0 (bS init 1)
    v.y = (float)bm;                         // mi in [0,100) exact in float
    g_pk[(size_t)b * KK + k] = v;            // single STG.64
}

// ---------------------------------------------------------------------------
// Kernel 1: per-(image, proposal) max-IoU matching.  (R14, unchanged)
// ---------------------------------------------------------------------------
__global__ __launch_bounds__(256) void iou_kernel(const float* __restrict__ gt,
                                                  const float* __restrict__ prop) {
    const int b   = blockIdx.y;
    const int tid = threadIdx.x;
    __shared__ float4 sgt[MM];
    __shared__ float  sarea[MM];

    if (tid < MM) {
        float4 g = reinterpret_cast<const float4*>(gt)[b * MM + tid];
        sgt[tid]   = g;
        sarea[tid] = (g.z - g.x) * (g.w - g.y);
    }
    __syncthreads();

    const float4* pr = reinterpret_cast<const float4*>(prop) + (size_t)b * NN;

    const int k0 = blockIdx.x * 256 + tid;   // [0, 2304) -> always a proposal (< NN)
    const int k1 = k0 + LPI;                 // [2304, 4608) -> may be gt or OOB
    float4 a0 = pr[k0];
    bool has1 = (k1 < KK);
    float4 a1 = a0;
    if (has1) a1 = (k1 < NN) ? pr[k1] : sgt[k1 - NN];

    float areaA0 = (a0.z - a0.x) * (a0.w - a0.y);
    float areaA1 = (a1.z - a1.x) * (a1.w - a1.y);

    // chains: [proposal][parity]; bS holds S (=areaG+areaA) of current best
    float bi0e = 0.f, bS0e = 1.f; int bm0e = 0;
    float bi0o = 0.f, bS0o = 1.f; int bm0o = 1;
    float bi1e = 0.f, bS1e = 1.f; int bm1e = 0;
    float bi1o = 0.f, bS1o = 1.f; int bm1o = 1;

    #pragma unroll 4
    for (int m = 0; m < MM; m += 2) {
        {
            float4 g = sgt[m];
            float ga = sarea[m];
            iou_upd(g.x, g.y, g.z, g.w, ga + areaA0, a0, bi0e, bS0e, bm0e, m);
            iou_upd(g.x, g.y, g.z, g.w, ga + areaA1, a1, bi1e, bS1e, bm1e, m);
        }
        {
            float4 g = sgt[m + 1];
            float ga = sarea[m + 1];
            iou_upd(g.x, g.y, g.z, g.w, ga + areaA0, a0, bi0o, bS0o, bm0o, m + 1);
            iou_upd(g.x, g.y, g.z, g.w, ga + areaA1, a1, bi1o, bS1o, bm1o, m + 1);
        }
    }

    // merge parities (first-max tie-break: equal value -> lower index)
    {
        float c0 = bi0e * bS0o, c1 = bi0o * bS0e;
        bool useE = (c0 > c1) || (c0 == c1 && bm0e < bm0o);
        iou_finish(useE ? bi0e : bi0o, useE ? bS0e : bS0o, useE ? bm0e : bm0o, b, k0);
    }
    if (has1) {
        float c0 = bi1e * bS1o, c1 = bi1o * bS1e;
        bool useE = (c0 > c1) || (c0 == c1 && bm1e < bm1o);
        iou_finish(useE ? bi1e : bi1o, useE ? bS1e : bS1o, useE ? bm1e : bm1o, b, k1);
    }
}

// ---------------------------------------------------------------------------
// Kernel 2: per-image fg/bg subsampling, SPLIT 2 CTAs per image (R14),
// now launched with Programmatic Dependent Launch: the iou-independent
// preamble (histogram zero, dtype detect, priority loads into smem) runs
// OVERLAPPED with iou_kernel's tail; cudaGridDependencySynchronize() gates
// the first g_pk read.
// ---------------------------------------------------------------------------
__global__ __launch_bounds__(ST) void sample_kernel(const float* __restrict__ pri,
                                                    const void*  __restrict__ gtcls,
                                                    float* __restrict__ out) {
    const int  b    = blockIdx.x;
    const bool isbg = (blockIdx.y != 0);
    const int  tid  = threadIdx.x;

    __shared__ float          s_pri[KK];
    __shared__ unsigned short s_list[KK];
    __shared__ int            s_cnt[NB];      // histogram, then scatter cursor
    __shared__ int            s_P[NB + 1];    // ascending exclusive prefix
    __shared__ unsigned short s_ord[BATCH_PER_IMG];
    __shared__ int            s_wsum[33];
    __shared__ int            s_nz;
    __shared__ int            s_nown;         // #elements of own group
    __shared__ int            s_cbg;          // #own elements with p >= TBF

    if (tid == 0) { s_nz = 0; s_nown = 0; s_cbg = 0; }
    s_cnt[tid] = 0;                           // NB == ST: one store per thread
    __syncthreads();

    // ---- pre-sync phase: independent of iou_kernel output ----
    // fg CTA only: gt_classes dtype detect (int64 -> high words all zero).
    if (!isbg && tid < 64) {
        const int* w = (const int*)gtcls;
        if (w[2 * tid + 1] != 0) atomicOr(&s_nz, 1);
    }

    const float*  prib = pri  + (size_t)b * KK;
    const float2* pkb  = g_pk + (size_t)b * KK;

    // P0a: load priorities into smem + registers.
    float pv[SIT];
    #pragma unroll
    for (int it = 0; it < SIT; it++) {
        int k = tid + it * ST;
        float p = -1.f;
        if (k < KK) {
            p = prib[k];
            s_pri[k] = p;
        }
        pv[it] = p;
    }

    // ---- wait for iou_kernel completion (PDL) ----
    cudaGridDependencySynchronize();

    // P0b: fg flags from g_pk; ballot-count group size and above-threshold
    // candidates (one shared atomic per warp).
    bool ov[SIT];
    unsigned nown = 0, cbg = 0;
    #pragma unroll
    for (int it = 0; it < SIT; it++) {
        int k = tid + it * ST;
        bool own = false;
        if (k < KK) {
            bool fg = (pkb[k].x >= 0.5f);
            own = isbg ? !fg : fg;
        }
        ov[it] = own;
        unsigned m1 = __ballot_sync(0xffffffffu, own);
        unsigned m2 = __ballot_sync(0xffffffffu, own && pv[it] >= TBF);
        if ((tid & 31) == 0) { nown += __popc(m1); cbg += __popc(m2); }
    }
    if ((tid & 31) == 0) {
        if (nown) atomicAdd(&s_nown, (int)nown);
        if (cbg)  atomicAdd(&s_cbg, (int)cbg);
    }
    __syncthreads();

    // bg: threshold valid iff >= 512 bg have p >= TBF (then top-512 bg all
    // have p >= TBF; excluded are strictly lower). fg: all elements included.
    const float tbeff = (isbg && s_cbg >= BATCH_PER_IMG) ? TBF : -1e30f;

    // P1: histogram own candidates.
    short myb[SIT];
    #pragma unroll
    for (int it = 0; it < SIT; it++) {
        short bs = -1;
        if (ov[it] && pv[it] >= tbeff) {
            int bk = (int)(pv[it] * (float)NB);
            bk = bk < 0 ? 0 : (bk > NB - 1 ? NB - 1 : bk);
            bs = (short)bk;
            atomicAdd(&s_cnt[bk], 1);
        }
        myb[it] = bs;
    }
    __syncthreads();

    // Exclusive scan over NB=1024 counts (1 per thread).
    int v = s_cnt[tid];
    int lane = tid & 31, wid = tid >> 5;
    int incl = v;
    #pragma unroll
    for (int d = 1; d < 32; d <<= 1) {
        int n = __shfl_up_sync(0xffffffffu, incl, d);
        if (lane >= d) incl += n;
    }
    if (lane == 31) s_wsum[wid] = incl;
    __syncthreads();
    if (tid == 0) {
        int s = 0;
        #pragma unroll
        for (int i = 0; i < 32; i++) { int c = s_wsum[i]; s_wsum[i] = s; s += c; }
        s_wsum[32] = s;
    }
    __syncthreads();
    int ex = s_wsum[wid] + incl - v;
    s_P[tid]  = ex;
    s_cnt[tid] = ex;                    // scatter cursor
    if (tid == 0) s_P[NB] = s_wsum[32];
    __syncthreads();

    const int candTot = s_P[NB];
    const int limit   = isbg ? BATCH_PER_IMG : NUM_FG_TARGET;

    // P2: scatter candidate indices into buckets.
    #pragma unroll
    for (int it = 0; it < SIT; it++) {
        if (myb[it] >= 0) {
            int k = tid + it * ST;
            int pos = atomicAdd(&s_cnt[myb[it]], 1);
            s_list[pos] = (unsigned short)k;
        }
    }
    __syncthreads();

    // P3: exact descending rank (higher bucket = higher priority); tie-break
    // = reversed stable argsort: equal priority -> higher index first.
    #pragma unroll
    for (int it = 0; it < SIT; it++) {
        if (myb[it] >= 0) {
            int bk = myb[it];
            int lo = s_P[bk], hi = s_P[bk + 1];
            int base = candTot - hi;        // candidates in strictly-higher buckets
            if (base < limit) {
                int k = tid + it * ST;
                float p = pv[it];
                int r = base;
                for (int j = lo; j < hi; j++) {
                    int o = s_list[j];
                    float po = s_pri[o];
                    if (po > p || (po == p && o > k)) r++;
                }
                if (r < limit) s_ord[r] = (unsigned short)k;
            }
        }
    }
    __syncthreads();

    // Output. Both CTAs derive num_fg from their own group count.
    const int nfg    = isbg ? (KK - s_nown) : s_nown;
    const int num_fg = nfg < NUM_FG_TARGET ? nfg : NUM_FG_TARGET;
    const int S    = BB * BATCH_PER_IMG;
    const int base = b * BATCH_PER_IMG + tid;

    if (!isbg) {
        // fg rows [0, num_fg): always valid, mv >= 0.5 so class from gt.
        if (tid < num_fg) {
            int k  = (int)s_ord[tid];
            float2 pk = pkb[k];               // one LDG.64: {mv, mi}
            int   mi = (int)pk.y;
            int cls = (s_nz == 0) ? (int)((const long long*)gtcls)[b * MM + mi]
                                  : ((const int*)gtcls)[b * MM + mi];
            out[base]         = pk.x;
            out[S + base]     = (float)k;
            out[2 * S + base] = (float)cls;
            out[3 * S + base] = pk.y;
            out[4 * S + base] = 1.f;
        }
    } else {
        // bg rows [num_fg, 512) incl. invalid tail; bg class is NCLS.
        if (tid >= num_fg && tid < BATCH_PER_IMG) {
            int nbg    = KK - nfg;
            int rem    = BATCH_PER_IMG - num_fg;
            int num_bg = nbg < rem ? nbg : rem;
            int tot    = num_fg + num_bg;
            float o_iou = 0.f;
            float o_idx = -1.f, o_cls = -1.f, o_gt = -1.f, o_val = 0.f;
            if (tid < tot) {
                int k = (int)s_ord[tid - num_fg];
                float2 pk = pkb[k];           // one LDG.64: {mv, mi}
                o_iou = pk.x;
                o_idx = (float)k;
                o_cls = (float)NCLS;
                o_gt  = pk.y;
                o_val = 1.f;
            }
            out[base]         = o_iou;
            out[S + base]     = o_idx;
            out[2 * S + base] = o_cls;
            out[3 * S + base] = o_gt;
            out[4 * S + base] = o_val;
        }
    }
}

// ---------------------------------------------------------------------------
extern "C" void kernel_launch(void* const* d_in, const int* in_sizes, int n_in,
                              void* d_out, int out_size) {
    const float* gt   = (const float*)d_in[0];   // [B, M, 4]
    const float* prop = (const float*)d_in[1];   // [B, N, 4]
    const void*  gtc  = d_in[2];                 // [B, M] int64 or int32
    const float* pri  = (const float*)d_in[3];   // [B, K]
    float* out = (float*)d_out;

    iou_kernel<<<dim3(9, BB), 256>>>(gt, prop);

    // Programmatic Dependent Launch: sample_kernel starts while iou_kernel
    // drains; its preamble is iou-independent, and it gates g_pk reads with
    // cudaGridDependencySynchronize().
    cudaLaunchConfig_t cfg = {};
    cfg.gridDim  = dim3(BB, 2);
    cfg.blockDim = dim3(ST);
    cfg.dynamicSmemBytes = 0;
    cfg.stream = 0;
    cudaLaunchAttribute attrs[1];
    attrs[0].id = cudaLaunchAttributeProgrammaticStreamSerialization;
    attrs[0].val.programmaticStreamSerializationAllowed = 1;
    cfg.attrs = attrs;
    cfg.numAttrs = 1;
    cudaLaunchKernelEx(&cfg, sample_kernel, pri, gtc, out);
}